// round 13
// baseline (speedup 1.0000x reference)
#include <cuda_runtime.h>

// OldNoiseConv: y[o,p] = b[o] + sum_i W[o,i] * x[i,p] * (1 + 0.1*eps[p,o,i])
// eps [32768,64,64] fp32 = 512MB read-once -> memory-bound.
//
// TERMINAL KERNEL (R10 config, profile reproduced twice: ncu 81.3/81.5us,
// HBM 6755 GB/s both runs). Sits at the B300 full-chip LTS throughput cap
// (~6300 B/cyc, path-independent) -- the achievable memory ceiling, not the
// 8 TB/s HBM spec. All axes experimentally bracketed across R1-R12:
//   granularity: 4096 blocks x 8pt x 256thr (persistent/-coarser/-finer all regress)
//   eps pipeline: depth-4 register prefetch, issued before staging+sync
//   cache policy: default (streaming hints regress)
//   staging/flush: float4

#define P_TOT    32768
#define NCH      64
#define PPB      8
#define NB       (P_TOT / PPB)     // 4096
#define NTHREADS 256
#define WPAD     68
#define YPAD     12                // ys row stride (floats), 16B-aligned rows

__global__ __launch_bounds__(NTHREADS, 4)
void noise_conv_kernel(const float* __restrict__ x,
                       const float* __restrict__ W,
                       const float* __restrict__ b,
                       const float* __restrict__ eps,
                       float* __restrict__ out)
{
    __shared__ float Ws[NCH][WPAD];
    __shared__ float xs[PPB][WPAD];
    __shared__ __align__(16) float ys[NCH][YPAD];
    __shared__ float bs[NCH];

    const int t  = threadIdx.x;
    const int w  = t >> 5;
    const int l  = t & 31;
    const int r4 = l >> 3;    // which of 4 output rows this pass
    const int c8 = l & 7;     // float4 column within row half
    const int p0 = blockIdx.x * PPB;
    const int p  = p0 + w;    // this warp's point

    // ---- eps prefetch FIRST (independent of smem): DRAM streams from cycle 0
    const float4* ep = reinterpret_cast<const float4*>(eps) + (size_t)p * 1024;
    float4 A0 = __ldcs(ep + ((0 * 4 + r4) << 4) + c8);
    float4 A1 = __ldcs(ep + ((0 * 4 + r4) << 4) + 8 + c8);
    float4 B0 = __ldcs(ep + ((1 * 4 + r4) << 4) + c8);
    float4 B1 = __ldcs(ep + ((1 * 4 + r4) << 4) + 8 + c8);
    float4 C0 = __ldcs(ep + ((2 * 4 + r4) << 4) + c8);
    float4 C1 = __ldcs(ep + ((2 * 4 + r4) << 4) + 8 + c8);
    float4 D0 = __ldcs(ep + ((3 * 4 + r4) << 4) + c8);
    float4 D1 = __ldcs(ep + ((3 * 4 + r4) << 4) + 8 + c8);

    // ---- stage x via float4 (also DRAM): row i, half h -> xs[4h..4h+3][i]
    if (t < 128) {
        const int i = t >> 1;          // channel 0..63
        const int h = t & 1;           // which float4 of the 8-point run
        const float4 v = *reinterpret_cast<const float4*>(
            &x[(size_t)i * P_TOT + p0 + (h << 2)]);
        xs[(h << 2) + 0][i] = v.x;
        xs[(h << 2) + 1][i] = v.y;
        xs[(h << 2) + 2][i] = v.z;
        xs[(h << 2) + 3][i] = v.w;
    }

    // ---- stage W (L2-hot after wave 1) via float4 (4 per thread)
    {
        const float4* Wv = reinterpret_cast<const float4*>(W);
        #pragma unroll
        for (int r = 0; r < 4; r++) {
            int idx = r * NTHREADS + t;
            *reinterpret_cast<float4*>(&Ws[idx >> 4][(idx & 15) << 2]) = Wv[idx];
        }
    }
    if (t < NCH) bs[t] = b[t];
    __syncthreads();

    const float4* xr  = reinterpret_cast<const float4*>(&xs[w][0]);
    const float4  xv0 = xr[c8];
    const float4  xv1 = xr[8 + c8];

    // ---- 16 passes, depth-4 register pipeline on eps
    #pragma unroll
    for (int pass = 0; pass < 16; pass++) {
        const int o = (pass << 2) + r4;

        float4 N0, N1;
        if (pass < 12) {
            const int off = (((pass + 4) << 2) + r4) << 4;
            N0 = __ldcs(ep + off + c8);
            N1 = __ldcs(ep + off + 8 + c8);
        }

        const float4* wr = reinterpret_cast<const float4*>(&Ws[o][0]);
        const float4 w0 = wr[c8];
        const float4 w1 = wr[8 + c8];

        float s0 = (w0.x * xv0.x) * fmaf(A0.x, 0.1f, 1.0f);
        float s1 = (w0.y * xv0.y) * fmaf(A0.y, 0.1f, 1.0f);
        s0 = fmaf(w0.z * xv0.z, fmaf(A0.z, 0.1f, 1.0f), s0);
        s1 = fmaf(w0.w * xv0.w, fmaf(A0.w, 0.1f, 1.0f), s1);
        s0 = fmaf(w1.x * xv1.x, fmaf(A1.x, 0.1f, 1.0f), s0);
        s1 = fmaf(w1.y * xv1.y, fmaf(A1.y, 0.1f, 1.0f), s1);
        s0 = fmaf(w1.z * xv1.z, fmaf(A1.z, 0.1f, 1.0f), s0);
        s1 = fmaf(w1.w * xv1.w, fmaf(A1.w, 0.1f, 1.0f), s1);
        float s = s0 + s1;

        s += __shfl_xor_sync(0xffffffffu, s, 1);
        s += __shfl_xor_sync(0xffffffffu, s, 2);
        s += __shfl_xor_sync(0xffffffffu, s, 4);

        if (c8 == 0) ys[o][w] = s;

        A0 = B0; A1 = B1;
        B0 = C0; B1 = C1;
        C0 = D0; C1 = D1;
        D0 = N0; D1 = N1;
    }
    __syncthreads();

    // ---- flush via float4: row o, half h -> out[o*P + p0 + 4h ..], add bias
    if (t < 128) {
        const int o = t >> 1;
        const int h = t & 1;
        const float4 v = *reinterpret_cast<const float4*>(&ys[o][h << 2]);
        const float bb = bs[o];
        float4 r;
        r.x = v.x + bb; r.y = v.y + bb; r.z = v.z + bb; r.w = v.w + bb;
        *reinterpret_cast<float4*>(&out[(size_t)o * P_TOT + p0 + (h << 2)]) = r;
    }
}

extern "C" void kernel_launch(void* const* d_in, const int* in_sizes, int n_in,
                              void* d_out, int out_size)
{
    const float* x   = (const float*)d_in[0];
    const float* W   = (const float*)d_in[1];
    const float* b   = (const float*)d_in[2];
    const float* eps = (const float*)d_in[3];
    float* out = (float*)d_out;
    (void)in_sizes; (void)n_in; (void)out_size;

    noise_conv_kernel<<<NB, NTHREADS>>>(x, W, b, eps, out);
}

// round 14
// speedup vs baseline: 1.0051x; 1.0051x over previous
#include <cuda_runtime.h>

// OldNoiseConv: y[o,p] = b[o] + sum_i W[o,i] * x[i,p] * (1 + 0.1*eps[p,o,i])
// eps [32768,64,64] fp32 = 512MB read-once -> memory-bound.
//
// TERMINAL KERNEL (profile reproduced 3x: ncu 81.3/81.5/82.6us, HBM
// 6.66-6.76 TB/s). Runs at ~85% DRAM utilization -- the characteristic
// HBM3e efficiency for a 97%-read stream -- and 95-96% of the compulsory
// 528MB traffic floor. All axes bracketed across R1-R13:
//   granularity: 4096 blocks x 8pt x 256thr, 4 CTAs/SM, 6.92 waves
//     (persistent / coarser / finer / 2pt-per-warp all regress >= 3us)
//   eps pipeline: depth-4 register prefetch, issued before staging+sync
//   cache policy: default stores (streaming hints regress)
//   staging/flush: float4

#define P_TOT    32768
#define NCH      64
#define PPB      8
#define NB       (P_TOT / PPB)     // 4096
#define NTHREADS 256
#define WPAD     68
#define YPAD     12                // ys row stride (floats), 16B-aligned rows

__global__ __launch_bounds__(NTHREADS, 4)
void noise_conv_kernel(const float* __restrict__ x,
                       const float* __restrict__ W,
                       const float* __restrict__ b,
                       const float* __restrict__ eps,
                       float* __restrict__ out)
{
    __shared__ float Ws[NCH][WPAD];
    __shared__ float xs[PPB][WPAD];
    __shared__ __align__(16) float ys[NCH][YPAD];
    __shared__ float bs[NCH];

    const int t  = threadIdx.x;
    const int w  = t >> 5;
    const int l  = t & 31;
    const int r4 = l >> 3;    // which of 4 output rows this pass
    const int c8 = l & 7;     // float4 column within row half
    const int p0 = blockIdx.x * PPB;
    const int p  = p0 + w;    // this warp's point

    // ---- eps prefetch FIRST (independent of smem): DRAM streams from cycle 0
    const float4* ep = reinterpret_cast<const float4*>(eps) + (size_t)p * 1024;
    float4 A0 = __ldcs(ep + ((0 * 4 + r4) << 4) + c8);
    float4 A1 = __ldcs(ep + ((0 * 4 + r4) << 4) + 8 + c8);
    float4 B0 = __ldcs(ep + ((1 * 4 + r4) << 4) + c8);
    float4 B1 = __ldcs(ep + ((1 * 4 + r4) << 4) + 8 + c8);
    float4 C0 = __ldcs(ep + ((2 * 4 + r4) << 4) + c8);
    float4 C1 = __ldcs(ep + ((2 * 4 + r4) << 4) + 8 + c8);
    float4 D0 = __ldcs(ep + ((3 * 4 + r4) << 4) + c8);
    float4 D1 = __ldcs(ep + ((3 * 4 + r4) << 4) + 8 + c8);

    // ---- stage x via float4 (also DRAM): row i, half h -> xs[4h..4h+3][i]
    if (t < 128) {
        const int i = t >> 1;          // channel 0..63
        const int h = t & 1;           // which float4 of the 8-point run
        const float4 v = *reinterpret_cast<const float4*>(
            &x[(size_t)i * P_TOT + p0 + (h << 2)]);
        xs[(h << 2) + 0][i] = v.x;
        xs[(h << 2) + 1][i] = v.y;
        xs[(h << 2) + 2][i] = v.z;
        xs[(h << 2) + 3][i] = v.w;
    }

    // ---- stage W (L2-hot after wave 1) via float4 (4 per thread)
    {
        const float4* Wv = reinterpret_cast<const float4*>(W);
        #pragma unroll
        for (int r = 0; r < 4; r++) {
            int idx = r * NTHREADS + t;
            *reinterpret_cast<float4*>(&Ws[idx >> 4][(idx & 15) << 2]) = Wv[idx];
        }
    }
    if (t < NCH) bs[t] = b[t];
    __syncthreads();

    const float4* xr  = reinterpret_cast<const float4*>(&xs[w][0]);
    const float4  xv0 = xr[c8];
    const float4  xv1 = xr[8 + c8];

    // ---- 16 passes, depth-4 register pipeline on eps
    #pragma unroll
    for (int pass = 0; pass < 16; pass++) {
        const int o = (pass << 2) + r4;

        float4 N0, N1;
        if (pass < 12) {
            const int off = (((pass + 4) << 2) + r4) << 4;
            N0 = __ldcs(ep + off + c8);
            N1 = __ldcs(ep + off + 8 + c8);
        }

        const float4* wr = reinterpret_cast<const float4*>(&Ws[o][0]);
        const float4 w0 = wr[c8];
        const float4 w1 = wr[8 + c8];

        float s0 = (w0.x * xv0.x) * fmaf(A0.x, 0.1f, 1.0f);
        float s1 = (w0.y * xv0.y) * fmaf(A0.y, 0.1f, 1.0f);
        s0 = fmaf(w0.z * xv0.z, fmaf(A0.z, 0.1f, 1.0f), s0);
        s1 = fmaf(w0.w * xv0.w, fmaf(A0.w, 0.1f, 1.0f), s1);
        s0 = fmaf(w1.x * xv1.x, fmaf(A1.x, 0.1f, 1.0f), s0);
        s1 = fmaf(w1.y * xv1.y, fmaf(A1.y, 0.1f, 1.0f), s1);
        s0 = fmaf(w1.z * xv1.z, fmaf(A1.z, 0.1f, 1.0f), s0);
        s1 = fmaf(w1.w * xv1.w, fmaf(A1.w, 0.1f, 1.0f), s1);
        float s = s0 + s1;

        s += __shfl_xor_sync(0xffffffffu, s, 1);
        s += __shfl_xor_sync(0xffffffffu, s, 2);
        s += __shfl_xor_sync(0xffffffffu, s, 4);

        if (c8 == 0) ys[o][w] = s;

        A0 = B0; A1 = B1;
        B0 = C0; B1 = C1;
        C0 = D0; C1 = D1;
        D0 = N0; D1 = N1;
    }
    __syncthreads();

    // ---- flush via float4: row o, half h -> out[o*P + p0 + 4h ..], add bias
    if (t < 128) {
        const int o = t >> 1;
        const int h = t & 1;
        const float4 v = *reinterpret_cast<const float4*>(&ys[o][h << 2]);
        const float bb = bs[o];
        float4 r;
        r.x = v.x + bb; r.y = v.y + bb; r.z = v.z + bb; r.w = v.w + bb;
        *reinterpret_cast<float4*>(&out[(size_t)o * P_TOT + p0 + (h << 2)]) = r;
    }
}

extern "C" void kernel_launch(void* const* d_in, const int* in_sizes, int n_in,
                              void* d_out, int out_size)
{
    const float* x   = (const float*)d_in[0];
    const float* W   = (const float*)d_in[1];
    const float* b   = (const float*)d_in[2];
    const float* eps = (const float*)d_in[3];
    float* out = (float*)d_out;
    (void)in_sizes; (void)n_in; (void)out_size;

    noise_conv_kernel<<<NB, NTHREADS>>>(x, W, b, eps, out);
}

// round 15
// speedup vs baseline: 1.0279x; 1.0227x over previous
#include <cuda_runtime.h>

// OldNoiseConv: y[o,p] = b[o] + sum_i W[o,i] * x[i,p] * (1 + 0.1*eps[p,o,i])
// eps [32768,64,64] fp32 = 512MB read-once -> memory-bound (~85% DRAM plateau).
// R15: direct in-loop stores. Warp w owns all 64 outputs of its point, so the
// reducing lanes store out[o*P+p] immediately (4B stores; the block's 8
// contiguous points cover each 32B sector, merged in L2 -> DRAM write traffic
// unchanged). Removes ys staging, the post-loop barrier, and the flush
// epilogue -- the last load-silent window per block. Everything else = R10.

#define P_TOT    32768
#define NCH      64
#define PPB      8
#define NB       (P_TOT / PPB)     // 4096
#define NTHREADS 256
#define WPAD     68

__global__ __launch_bounds__(NTHREADS, 4)
void noise_conv_kernel(const float* __restrict__ x,
                       const float* __restrict__ W,
                       const float* __restrict__ b,
                       const float* __restrict__ eps,
                       float* __restrict__ out)
{
    __shared__ float Ws[NCH][WPAD];
    __shared__ float xs[PPB][WPAD];
    __shared__ float bs[NCH];

    const int t  = threadIdx.x;
    const int w  = t >> 5;
    const int l  = t & 31;
    const int r4 = l >> 3;    // which of 4 output rows this pass
    const int c8 = l & 7;     // float4 column within row half
    const int p0 = blockIdx.x * PPB;
    const int p  = p0 + w;    // this warp's point

    // ---- eps prefetch FIRST (independent of smem): DRAM streams from cycle 0
    const float4* ep = reinterpret_cast<const float4*>(eps) + (size_t)p * 1024;
    float4 A0 = __ldcs(ep + ((0 * 4 + r4) << 4) + c8);
    float4 A1 = __ldcs(ep + ((0 * 4 + r4) << 4) + 8 + c8);
    float4 B0 = __ldcs(ep + ((1 * 4 + r4) << 4) + c8);
    float4 B1 = __ldcs(ep + ((1 * 4 + r4) << 4) + 8 + c8);
    float4 C0 = __ldcs(ep + ((2 * 4 + r4) << 4) + c8);
    float4 C1 = __ldcs(ep + ((2 * 4 + r4) << 4) + 8 + c8);
    float4 D0 = __ldcs(ep + ((3 * 4 + r4) << 4) + c8);
    float4 D1 = __ldcs(ep + ((3 * 4 + r4) << 4) + 8 + c8);

    // ---- stage x via float4 (also DRAM): row i, half h -> xs[4h..4h+3][i]
    if (t < 128) {
        const int i = t >> 1;          // channel 0..63
        const int h = t & 1;           // which float4 of the 8-point run
        const float4 v = *reinterpret_cast<const float4*>(
            &x[(size_t)i * P_TOT + p0 + (h << 2)]);
        xs[(h << 2) + 0][i] = v.x;
        xs[(h << 2) + 1][i] = v.y;
        xs[(h << 2) + 2][i] = v.z;
        xs[(h << 2) + 3][i] = v.w;
    }

    // ---- stage W (L2-hot after wave 1) via float4 (4 per thread)
    {
        const float4* Wv = reinterpret_cast<const float4*>(W);
        #pragma unroll
        for (int r = 0; r < 4; r++) {
            int idx = r * NTHREADS + t;
            *reinterpret_cast<float4*>(&Ws[idx >> 4][(idx & 15) << 2]) = Wv[idx];
        }
    }
    if (t < NCH) bs[t] = b[t];
    __syncthreads();

    const float4* xr  = reinterpret_cast<const float4*>(&xs[w][0]);
    const float4  xv0 = xr[c8];
    const float4  xv1 = xr[8 + c8];

    // ---- 16 passes, depth-4 register pipeline on eps, direct stores
    #pragma unroll
    for (int pass = 0; pass < 16; pass++) {
        const int o = (pass << 2) + r4;

        float4 N0, N1;
        if (pass < 12) {
            const int off = (((pass + 4) << 2) + r4) << 4;
            N0 = __ldcs(ep + off + c8);
            N1 = __ldcs(ep + off + 8 + c8);
        }

        const float4* wr = reinterpret_cast<const float4*>(&Ws[o][0]);
        const float4 w0 = wr[c8];
        const float4 w1 = wr[8 + c8];

        float s0 = (w0.x * xv0.x) * fmaf(A0.x, 0.1f, 1.0f);
        float s1 = (w0.y * xv0.y) * fmaf(A0.y, 0.1f, 1.0f);
        s0 = fmaf(w0.z * xv0.z, fmaf(A0.z, 0.1f, 1.0f), s0);
        s1 = fmaf(w0.w * xv0.w, fmaf(A0.w, 0.1f, 1.0f), s1);
        s0 = fmaf(w1.x * xv1.x, fmaf(A1.x, 0.1f, 1.0f), s0);
        s1 = fmaf(w1.y * xv1.y, fmaf(A1.y, 0.1f, 1.0f), s1);
        s0 = fmaf(w1.z * xv1.z, fmaf(A1.z, 0.1f, 1.0f), s0);
        s1 = fmaf(w1.w * xv1.w, fmaf(A1.w, 0.1f, 1.0f), s1);
        float s = s0 + s1;

        s += __shfl_xor_sync(0xffffffffu, s, 1);
        s += __shfl_xor_sync(0xffffffffu, s, 2);
        s += __shfl_xor_sync(0xffffffffu, s, 4);

        // direct store under load shadow: block's 8 points fill each 32B
        // sector of row o; L2 merges before eviction.
        if (c8 == 0) out[(size_t)o * P_TOT + p] = s + bs[o];

        A0 = B0; A1 = B1;
        B0 = C0; B1 = C1;
        C0 = D0; C1 = D1;
        D0 = N0; D1 = N1;
    }
    // no epilogue: no ys, no second barrier, no flush
}

extern "C" void kernel_launch(void* const* d_in, const int* in_sizes, int n_in,
                              void* d_out, int out_size)
{
    const float* x   = (const float*)d_in[0];
    const float* W   = (const float*)d_in[1];
    const float* b   = (const float*)d_in[2];
    const float* eps = (const float*)d_in[3];
    float* out = (float*)d_out;
    (void)in_sizes; (void)n_in; (void)out_size;

    noise_conv_kernel<<<NB, NTHREADS>>>(x, W, b, eps, out);
}

// round 16
// speedup vs baseline: 1.0835x; 1.0541x over previous
#include <cuda_runtime.h>

// OldNoiseConv: y[o,p] = b[o] + sum_i W[o,i] * x[i,p] * (1 + 0.1*eps[p,o,i])
// eps [32768,64,64] fp32 = 512MB read-once -> memory-bound.
// R16 = R15 (direct in-loop stores, no epilogue/2nd barrier; ncu 80.7us,
// DRAM 86.1%) + tail-pass L2 prefetch: passes 12-15 (register pipeline
// drained) issue prefetch.global.L2 for the eps warmup region of block
// bid+592 -- the next occupant of this SM slot -- filling the per-warp
// load-silent drain window with the successor's compulsory traffic.

#define P_TOT    32768
#define NCH      64
#define PPB      8
#define NB       (P_TOT / PPB)     // 4096
#define NTHREADS 256
#define WPAD     68
#define SLOTS    592               // 148 SMs x 4 CTAs: next wave occupant stride

__global__ __launch_bounds__(NTHREADS, 4)
void noise_conv_kernel(const float* __restrict__ x,
                       const float* __restrict__ W,
                       const float* __restrict__ b,
                       const float* __restrict__ eps,
                       float* __restrict__ out)
{
    __shared__ float Ws[NCH][WPAD];
    __shared__ float xs[PPB][WPAD];
    __shared__ float bs[NCH];

    const int t  = threadIdx.x;
    const int w  = t >> 5;
    const int l  = t & 31;
    const int r4 = l >> 3;    // which of 4 output rows this pass
    const int c8 = l & 7;     // float4 column within row half
    const int p0 = blockIdx.x * PPB;
    const int p  = p0 + w;    // this warp's point

    // ---- eps prefetch FIRST (independent of smem): DRAM streams from cycle 0
    const float4* ep = reinterpret_cast<const float4*>(eps) + (size_t)p * 1024;
    float4 A0 = __ldcs(ep + ((0 * 4 + r4) << 4) + c8);
    float4 A1 = __ldcs(ep + ((0 * 4 + r4) << 4) + 8 + c8);
    float4 B0 = __ldcs(ep + ((1 * 4 + r4) << 4) + c8);
    float4 B1 = __ldcs(ep + ((1 * 4 + r4) << 4) + 8 + c8);
    float4 C0 = __ldcs(ep + ((2 * 4 + r4) << 4) + c8);
    float4 C1 = __ldcs(ep + ((2 * 4 + r4) << 4) + 8 + c8);
    float4 D0 = __ldcs(ep + ((3 * 4 + r4) << 4) + c8);
    float4 D1 = __ldcs(ep + ((3 * 4 + r4) << 4) + 8 + c8);

    // ---- stage x via float4 (also DRAM): row i, half h -> xs[4h..4h+3][i]
    if (t < 128) {
        const int i = t >> 1;          // channel 0..63
        const int h = t & 1;           // which float4 of the 8-point run
        const float4 v = *reinterpret_cast<const float4*>(
            &x[(size_t)i * P_TOT + p0 + (h << 2)]);
        xs[(h << 2) + 0][i] = v.x;
        xs[(h << 2) + 1][i] = v.y;
        xs[(h << 2) + 2][i] = v.z;
        xs[(h << 2) + 3][i] = v.w;
    }

    // ---- stage W (L2-hot after wave 1) via float4 (4 per thread)
    {
        const float4* Wv = reinterpret_cast<const float4*>(W);
        #pragma unroll
        for (int r = 0; r < 4; r++) {
            int idx = r * NTHREADS + t;
            *reinterpret_cast<float4*>(&Ws[idx >> 4][(idx & 15) << 2]) = Wv[idx];
        }
    }
    if (t < NCH) bs[t] = b[t];
    __syncthreads();

    const float4* xr  = reinterpret_cast<const float4*>(&xs[w][0]);
    const float4  xv0 = xr[c8];
    const float4  xv1 = xr[8 + c8];

    // next-wave occupant of this slot: same warp/point layout, +SLOTS blocks
    const bool  pf_ok = (blockIdx.x + SLOTS) < NB;
    const float4* epn = ep + (size_t)SLOTS * PPB * 1024;

    // ---- 16 passes, depth-4 register pipeline on eps, direct stores
    #pragma unroll
    for (int pass = 0; pass < 16; pass++) {
        const int o = (pass << 2) + r4;

        float4 N0, N1;
        if (pass < 12) {
            const int off = (((pass + 4) << 2) + r4) << 4;
            N0 = __ldcs(ep + off + c8);
            N1 = __ldcs(ep + off + 8 + c8);
        } else if (pf_ok) {
            // drain window: warm L2 with successor block's warmup passes 0-3
            const int off = (((pass - 12) << 2) + r4) << 4;
            const float4* q0 = epn + off + c8;
            const float4* q1 = epn + off + 8 + c8;
            asm volatile("prefetch.global.L2 [%0];" :: "l"(q0));
            asm volatile("prefetch.global.L2 [%0];" :: "l"(q1));
        }

        const float4* wr = reinterpret_cast<const float4*>(&Ws[o][0]);
        const float4 w0 = wr[c8];
        const float4 w1 = wr[8 + c8];

        float s0 = (w0.x * xv0.x) * fmaf(A0.x, 0.1f, 1.0f);
        float s1 = (w0.y * xv0.y) * fmaf(A0.y, 0.1f, 1.0f);
        s0 = fmaf(w0.z * xv0.z, fmaf(A0.z, 0.1f, 1.0f), s0);
        s1 = fmaf(w0.w * xv0.w, fmaf(A0.w, 0.1f, 1.0f), s1);
        s0 = fmaf(w1.x * xv1.x, fmaf(A1.x, 0.1f, 1.0f), s0);
        s1 = fmaf(w1.y * xv1.y, fmaf(A1.y, 0.1f, 1.0f), s1);
        s0 = fmaf(w1.z * xv1.z, fmaf(A1.z, 0.1f, 1.0f), s0);
        s1 = fmaf(w1.w * xv1.w, fmaf(A1.w, 0.1f, 1.0f), s1);
        float s = s0 + s1;

        s += __shfl_xor_sync(0xffffffffu, s, 1);
        s += __shfl_xor_sync(0xffffffffu, s, 2);
        s += __shfl_xor_sync(0xffffffffu, s, 4);

        // direct store under load shadow: block's 8 points fill each 32B
        // sector of row o; L2 merges before eviction.
        if (c8 == 0) out[(size_t)o * P_TOT + p] = s + bs[o];

        A0 = B0; A1 = B1;
        B0 = C0; B1 = C1;
        C0 = D0; C1 = D1;
        D0 = N0; D1 = N1;
    }
    // no epilogue: no ys, no second barrier, no flush
}

extern "C" void kernel_launch(void* const* d_in, const int* in_sizes, int n_in,
                              void* d_out, int out_size)
{
    const float* x   = (const float*)d_in[0];
    const float* W   = (const float*)d_in[1];
    const float* b   = (const float*)d_in[2];
    const float* eps = (const float*)d_in[3];
    float* out = (float*)d_out;
    (void)in_sizes; (void)n_in; (void)out_size;

    noise_conv_kernel<<<NB, NTHREADS>>>(x, W, b, eps, out);
}